// round 4
// baseline (speedup 1.0000x reference)
#include <cuda_runtime.h>
#include <cstdint>

// CausalQueue: out[b, 0:C]  = (size == D) ? buffer[head, b, :] : 0
//              out[b, C:2C] = x[b, :]
// x: [B, C] f32, buffer: [D, B, C] f32, size/head: int32 scalars (device).
// D=128, B=2048, C=512. Output [B, 2C] f32 = 8 MB.
//
// Pure streaming copy: 16 MB total HBM traffic. One thread per float4 of
// output; uniform branch on (size == D) read from device scalars.

#define D_CAP 128
#define B_DIM 2048
#define C_DIM 512

// float4 counts
#define C4       (C_DIM / 4)        // 128 float4 per half-row
#define ROW4     (2 * C4)           // 256 float4 per output row
#define TOTAL4   (B_DIM * ROW4)     // 524288 float4 total

__global__ void __launch_bounds__(256, 8)
causal_queue_kernel(const float4* __restrict__ x,
                    const float4* __restrict__ buffer,
                    const int* __restrict__ size_p,
                    const int* __restrict__ head_p,
                    float4* __restrict__ out)
{
    const int i = blockIdx.x * blockDim.x + threadIdx.x;   // 0 .. TOTAL4-1
    if (i >= TOTAL4) return;

    const int row  = i >> 8;          // / ROW4 (256)
    const int col4 = i & 255;         // % ROW4

    // Uniform across the whole grid: no divergence.
    const int  head = *head_p;
    const bool full = (*size_p == D_CAP);

    float4 v;
    if (col4 < C4) {
        // past half: buffer[head, row, col4*4 ..]
        if (full) {
            v = buffer[(size_t)head * (B_DIM * C4) + (size_t)row * C4 + col4];
        } else {
            v = make_float4(0.f, 0.f, 0.f, 0.f);
        }
    } else {
        // x half
        v = x[(size_t)row * C4 + (col4 - C4)];
    }
    out[i] = v;
}

extern "C" void kernel_launch(void* const* d_in, const int* in_sizes, int n_in,
                              void* d_out, int out_size)
{
    const float4* x      = (const float4*)d_in[0];   // [B, C] f32
    const float4* buffer = (const float4*)d_in[1];   // [D, B, C] f32
    const int*    size_p = (const int*)d_in[2];      // scalar
    const int*    head_p = (const int*)d_in[3];      // scalar
    float4*       out    = (float4*)d_out;           // [B, 2C] f32

    const int threads = 256;
    const int blocks  = (TOTAL4 + threads - 1) / threads;  // 2048
    causal_queue_kernel<<<blocks, threads>>>(x, buffer, size_p, head_p, out);
}

// round 5
// speedup vs baseline: 1.0048x; 1.0048x over previous
#include <cuda_runtime.h>
#include <cstdint>

// CausalQueue: out[b, 0:C]  = (size == D) ? buffer[head, b, :] : 0
//              out[b, C:2C] = x[b, :]
// x: [B, C] f32, buffer: [D, B, C] f32, size/head: int32 scalars (device).
// D=128, B=2048, C=512. Output [B, 2C] f32 = 8 MB; 16 MB total HBM traffic.
//
// R4: MLP=8 per thread. One block (256 thr) covers 8 full output rows:
// lane t = column t of the row (t<128 -> past half, t>=128 -> x half),
// k = 0..7 selects the row. All 8 loads are independent -> deep LSU queue.
// Scalars are read only by past-half threads (uniform, L1-hit).

#define D_CAP  128
#define B_DIM  2048
#define C_DIM  512
#define C4     (C_DIM / 4)      // 128 float4 per half-row
#define ROW4   (2 * C4)         // 256 float4 per output row
#define RPB    8                // rows per block

__global__ void __launch_bounds__(256)
causal_queue_kernel(const float4* __restrict__ x,
                    const float4* __restrict__ buffer,
                    const int* __restrict__ size_p,
                    const int* __restrict__ head_p,
                    float4* __restrict__ out)
{
    const int t    = threadIdx.x;            // 0..255
    const int row0 = blockIdx.x * RPB;       // first of 8 rows

    float4 v[RPB];

    if (t < C4) {
        // ---- past half: column t of buffer[head] (or zeros) ----
        const int  head = __ldg(head_p);
        const bool full = (__ldg(size_p) == D_CAP);
        if (full) {
            const float4* src = buffer + (size_t)head * (B_DIM * C4)
                                       + (size_t)row0 * C4 + t;
#pragma unroll
            for (int k = 0; k < RPB; k++) v[k] = src[k * C4];
        } else {
#pragma unroll
            for (int k = 0; k < RPB; k++) v[k] = make_float4(0.f, 0.f, 0.f, 0.f);
        }
#pragma unroll
        for (int k = 0; k < RPB; k++)
            out[(size_t)(row0 + k) * ROW4 + t] = v[k];
    } else {
        // ---- x half: column (t - C4) of x ----
        const int c = t - C4;
        const float4* src = x + (size_t)row0 * C4 + c;
#pragma unroll
        for (int k = 0; k < RPB; k++) v[k] = src[k * C4];
#pragma unroll
        for (int k = 0; k < RPB; k++)
            out[(size_t)(row0 + k) * ROW4 + C4 + c] = v[k];
    }
}

extern "C" void kernel_launch(void* const* d_in, const int* in_sizes, int n_in,
                              void* d_out, int out_size)
{
    const float4* x      = (const float4*)d_in[0];   // [B, C] f32
    const float4* buffer = (const float4*)d_in[1];   // [D, B, C] f32
    const int*    size_p = (const int*)d_in[2];      // scalar
    const int*    head_p = (const int*)d_in[3];      // scalar
    float4*       out    = (float4*)d_out;           // [B, 2C] f32

    causal_queue_kernel<<<B_DIM / RPB, 256>>>(x, buffer, size_p, head_p, out);
}

// round 8
// speedup vs baseline: 1.0097x; 1.0049x over previous
#include <cuda_runtime.h>
#include <cstdint>

// CausalQueue: out[b, 0:C]  = (size == D) ? buffer[head, b, :] : 0
//              out[b, C:2C] = x[b, :]
// x: [B,C] f32, buffer: [D,B,C] f32, size/head int32 device scalars.
// D=128, B=2048, C=512. 16 MB total traffic.
//
// R5: route everything through the async proxy (cp.async.bulk), bypassing
// the LSU/L1tex wavefront path. Per block (4 rows): 2 bulk loads (8 KB
// past chunk + 8 KB x chunk, both contiguous in GMEM) -> smem, mbarrier
// wait, then 8 x 2 KB bulk stores into the interleaved output rows.
// ~18 issued instructions per block total.

#define D_CAP     128
#define B_DIM     2048
#define C_DIM     512
#define ROW_BYTES (C_DIM * 4)          // 2048 B per half-row
#define RPB       4                    // rows per block
#define GRID      (B_DIM / RPB)        // 512 blocks
#define CHUNK     (RPB * ROW_BYTES)    // 8192 B per half-chunk

__device__ __forceinline__ uint32_t smem_u32(const void* p) {
    return (uint32_t)__cvta_generic_to_shared(p);
}

__global__ void __launch_bounds__(128)
causal_queue_tma(const char* __restrict__ x,
                 const char* __restrict__ buffer,
                 const int* __restrict__ size_p,
                 const int* __restrict__ head_p,
                 char* __restrict__ out)
{
    __shared__ __align__(128) char s_past[CHUNK];
    __shared__ __align__(128) char s_x[CHUNK];
    __shared__ __align__(8)   uint64_t mbar;

    const int t    = threadIdx.x;
    const int row0 = blockIdx.x * RPB;

    const int  head = __ldg(head_p);
    const bool full = (__ldg(size_p) == D_CAP);

    const uint32_t mbar_a = smem_u32(&mbar);

    if (t == 0) {
        asm volatile("mbarrier.init.shared.b64 [%0], 1;" :: "r"(mbar_a) : "memory");
    }
    __syncthreads();

    if (t == 0) {
        const uint32_t tx = full ? 2u * CHUNK : (uint32_t)CHUNK;
        asm volatile("mbarrier.arrive.expect_tx.shared.b64 _, [%0], %1;"
                     :: "r"(mbar_a), "r"(tx) : "memory");
        // x chunk: 4 contiguous rows of x
        asm volatile(
            "cp.async.bulk.shared::cluster.global.mbarrier::complete_tx::bytes "
            "[%0], [%1], %2, [%3];"
            :: "r"(smem_u32(s_x)),
               "l"(x + (size_t)row0 * ROW_BYTES),
               "r"((uint32_t)CHUNK), "r"(mbar_a) : "memory");
        if (full) {
            const char* src = buffer + (size_t)head * ((size_t)B_DIM * ROW_BYTES)
                                     + (size_t)row0 * ROW_BYTES;
            asm volatile(
                "cp.async.bulk.shared::cluster.global.mbarrier::complete_tx::bytes "
                "[%0], [%1], %2, [%3];"
                :: "r"(smem_u32(s_past)), "l"(src),
                   "r"((uint32_t)CHUNK), "r"(mbar_a) : "memory");
        }
    }

    if (!full) {
        // cold-start branch: zero the past chunk with all 128 threads
        float4* p = (float4*)s_past;
#pragma unroll
        for (int i = t; i < CHUNK / 16; i += 128)
            p[i] = make_float4(0.f, 0.f, 0.f, 0.f);
        __syncthreads();   // all threads (incl. t0) reach this in the !full path
    }

    if (t == 0) {
        // Wait for the bulk load(s) to complete (phase parity 0).
        asm volatile(
            "{\n\t"
            ".reg .pred P;\n\t"
            "WAIT_%=:\n\t"
            "mbarrier.try_wait.parity.shared.b64 P, [%0], 0;\n\t"
            "@P bra DONE_%=;\n\t"
            "bra WAIT_%=;\n\t"
            "DONE_%=:\n\t"
            "}"
            :: "r"(mbar_a) : "memory");

        // Order any generic smem writes (zero-fill path) before async-proxy reads.
        asm volatile("fence.proxy.async.shared::cta;" ::: "memory");

        // 8 bulk stores: interleave past|x per output row.
#pragma unroll
        for (int k = 0; k < RPB; k++) {
            char* dst = out + (size_t)(row0 + k) * (2 * ROW_BYTES);
            asm volatile(
                "cp.async.bulk.global.shared::cta.bulk_group [%0], [%1], %2;"
                :: "l"(dst), "r"(smem_u32(s_past + k * ROW_BYTES)),
                   "r"((uint32_t)ROW_BYTES) : "memory");
            asm volatile(
                "cp.async.bulk.global.shared::cta.bulk_group [%0], [%1], %2;"
                :: "l"(dst + ROW_BYTES), "r"(smem_u32(s_x + k * ROW_BYTES)),
                   "r"((uint32_t)ROW_BYTES) : "memory");
        }
        asm volatile("cp.async.bulk.commit_group;" ::: "memory");
        asm volatile("cp.async.bulk.wait_group 0;" ::: "memory");
    }
}

extern "C" void kernel_launch(void* const* d_in, const int* in_sizes, int n_in,
                              void* d_out, int out_size)
{
    const char* x      = (const char*)d_in[0];   // [B, C] f32
    const char* buffer = (const char*)d_in[1];   // [D, B, C] f32
    const int*  size_p = (const int*)d_in[2];    // scalar
    const int*  head_p = (const int*)d_in[3];    // scalar
    char*       out    = (char*)d_out;           // [B, 2C] f32

    causal_queue_tma<<<GRID, 128>>>(x, buffer, size_p, head_p, out);
}